// round 13
// baseline (speedup 1.0000x reference)
#include <cuda_runtime.h>
#include <cuda_bf16.h>
#include <cstdint>

#define HIDDEN 1024
#define NHEADS 16
#define HDIM   64
#define BATCH  2
#define SEQ    2048
#define MROWS  (BATCH*SEQ)   // 4096

// fp32 ctx scratch
__device__ float g_ctx[MROWS*HIDDEN];
// bf16 hi/lo planes produced by projection GEMM epilogues
__device__ __nv_bfloat16 g_Qbh[MROWS*HIDDEN];   // [BH][S][D], pre-scaled 1/8
__device__ __nv_bfloat16 g_Qbl[MROWS*HIDDEN];
__device__ __nv_bfloat16 g_Kbh[MROWS*HIDDEN];   // [BH][S][D]
__device__ __nv_bfloat16 g_Kbl[MROWS*HIDDEN];
__device__ __nv_bfloat16 g_Vbh[MROWS*HIDDEN];   // [BH][D][S]  (transposed)
__device__ __nv_bfloat16 g_Vbl[MROWS*HIDDEN];

// ---------------------------------------------------------------------------
__device__ __forceinline__ void mma16816(float* c, const uint32_t* a,
                                         const uint32_t* b)
{
    asm volatile(
        "mma.sync.aligned.m16n8k16.row.col.f32.bf16.bf16.f32 "
        "{%0,%1,%2,%3}, {%4,%5,%6,%7}, {%8,%9}, {%0,%1,%2,%3};"
        : "+f"(c[0]), "+f"(c[1]), "+f"(c[2]), "+f"(c[3])
        : "r"(a[0]), "r"(a[1]), "r"(a[2]), "r"(a[3]), "r"(b[0]), "r"(b[1]));
}

__device__ __forceinline__ uint32_t pack_bf16(__nv_bfloat16 lo, __nv_bfloat16 hi)
{
    __nv_bfloat162 t = __halves2bfloat162(lo, hi);
    return *(uint32_t*)&t;
}

__device__ __forceinline__ void split2(float x, float y,
                                       uint32_t& hi, uint32_t& lo)
{
    __nv_bfloat16 hx = __float2bfloat16_rn(x), hy = __float2bfloat16_rn(y);
    __nv_bfloat16 lx = __float2bfloat16_rn(x - __bfloat162float(hx));
    __nv_bfloat16 ly = __float2bfloat16_rn(y - __bfloat162float(hy));
    hi = pack_bf16(hx, hy);
    lo = pack_bf16(lx, ly);
}

__device__ __forceinline__ uint32_t s2u(const void* p) {
    uint32_t a;
    asm("{ .reg .u64 t; cvta.to.shared.u64 t, %1; cvt.u32.u64 %0, t; }"
        : "=r"(a) : "l"(p));
    return a;
}
__device__ __forceinline__ void cp_async16(uint32_t dst, const void* src) {
    asm volatile("cp.async.cg.shared.global [%0], [%1], 16;"
                 :: "r"(dst), "l"(src) : "memory");
}
__device__ __forceinline__ void cp_commit() {
    asm volatile("cp.async.commit_group;" ::: "memory");
}
__device__ __forceinline__ void cp_wait0() {
    asm volatile("cp.async.wait_group 0;" ::: "memory");
}

// ---------------------------------------------------------------------------
// C[4096,1024] = X @ W^T + bias via bf16 hi/lo split (3 MMA passes).
// Mainloop unchanged from R8 (measured good). Epilogues:
//  MODE 0: fp32 row-major to outF
//  MODE 1: bf16 hi/lo planes [BH][S][D], value = (acc+bias)*scale
//  MODE 2: bf16 hi/lo planes [BH][D][S] (transposed), value = acc+bias
// ---------------------------------------------------------------------------
template<int MODE>
__global__ __launch_bounds__(256)
void gemm_bf16x2(const float* __restrict__ X, const float* __restrict__ W,
                 const float* __restrict__ bias, float* __restrict__ outF,
                 __nv_bfloat16* __restrict__ outH,
                 __nv_bfloat16* __restrict__ outL, float scale)
{
    constexpr int BK = 32, ST = 40;
    extern __shared__ __nv_bfloat16 smb[];
    __nv_bfloat16* Ah = smb;
    __nv_bfloat16* Al = Ah + 128 * ST;
    __nv_bfloat16* Bh = Al + 128 * ST;
    __nv_bfloat16* Bl = Bh + 128 * ST;

    const int tid  = threadIdx.x;
    const int lane = tid & 31, warp = tid >> 5;
    const int wr = warp >> 2, wc = warp & 3;
    const int row0 = blockIdx.y * 128, col0 = blockIdx.x * 128;
    const int m0 = wr * 64, n0 = wc * 32;
    const int fr = lane >> 2, fc = lane & 3;

    float acc[4][4][4] = {};
    const int gr = tid >> 3, gc4 = tid & 7;

    for (int k0 = 0; k0 < HIDDEN; k0 += BK) {
        #pragma unroll
        for (int i = 0; i < 4; i++) {
            int r = gr + i * 32;
            float4 v = *(const float4*)&X[(size_t)(row0 + r) * HIDDEN + k0 + gc4 * 4];
            uint32_t h0, l0, h1, l1;
            split2(v.x, v.y, h0, l0); split2(v.z, v.w, h1, l1);
            *(uint32_t*)&Ah[r * ST + gc4 * 4]     = h0;
            *(uint32_t*)&Ah[r * ST + gc4 * 4 + 2] = h1;
            *(uint32_t*)&Al[r * ST + gc4 * 4]     = l0;
            *(uint32_t*)&Al[r * ST + gc4 * 4 + 2] = l1;

            v = *(const float4*)&W[(size_t)(col0 + r) * HIDDEN + k0 + gc4 * 4];
            split2(v.x, v.y, h0, l0); split2(v.z, v.w, h1, l1);
            *(uint32_t*)&Bh[r * ST + gc4 * 4]     = h0;
            *(uint32_t*)&Bh[r * ST + gc4 * 4 + 2] = h1;
            *(uint32_t*)&Bl[r * ST + gc4 * 4]     = l0;
            *(uint32_t*)&Bl[r * ST + gc4 * 4 + 2] = l1;
        }
        __syncthreads();

        #pragma unroll
        for (int ks = 0; ks < BK; ks += 16) {
            uint32_t ah[4][4], al[4][4], bh[4][2], bl[4][2];
            #pragma unroll
            for (int mi = 0; mi < 4; mi++) {
                const __nv_bfloat16* pa = &Ah[(m0 + mi * 16 + fr) * ST + ks + fc * 2];
                const __nv_bfloat16* pl = &Al[(m0 + mi * 16 + fr) * ST + ks + fc * 2];
                ah[mi][0] = *(const uint32_t*)pa;
                ah[mi][1] = *(const uint32_t*)(pa + 8 * ST);
                ah[mi][2] = *(const uint32_t*)(pa + 8);
                ah[mi][3] = *(const uint32_t*)(pa + 8 * ST + 8);
                al[mi][0] = *(const uint32_t*)pl;
                al[mi][1] = *(const uint32_t*)(pl + 8 * ST);
                al[mi][2] = *(const uint32_t*)(pl + 8);
                al[mi][3] = *(const uint32_t*)(pl + 8 * ST + 8);
            }
            #pragma unroll
            for (int ni = 0; ni < 4; ni++) {
                const __nv_bfloat16* pb = &Bh[(n0 + ni * 8 + fr) * ST + ks + fc * 2];
                const __nv_bfloat16* pl = &Bl[(n0 + ni * 8 + fr) * ST + ks + fc * 2];
                bh[ni][0] = *(const uint32_t*)pb;
                bh[ni][1] = *(const uint32_t*)(pb + 8);
                bl[ni][0] = *(const uint32_t*)pl;
                bl[ni][1] = *(const uint32_t*)(pl + 8);
            }
            #pragma unroll
            for (int mi = 0; mi < 4; mi++)
                #pragma unroll
                for (int ni = 0; ni < 4; ni++) {
                    mma16816(acc[mi][ni], ah[mi], bh[ni]);
                    mma16816(acc[mi][ni], ah[mi], bl[ni]);
                    mma16816(acc[mi][ni], al[mi], bh[ni]);
                }
        }
        __syncthreads();
    }

    #pragma unroll
    for (int mi = 0; mi < 4; mi++) {
        #pragma unroll
        for (int ni = 0; ni < 4; ni++) {
            int gm = row0 + m0 + mi * 16 + fr;
            int gn = col0 + n0 + ni * 8 + fc * 2;
            float b0 = bias[gn], b1 = bias[gn + 1];
            float2 v0 = make_float2(acc[mi][ni][0] + b0, acc[mi][ni][1] + b1);
            float2 v1 = make_float2(acc[mi][ni][2] + b0, acc[mi][ni][3] + b1);
            if (MODE == 0) {
                *(float2*)&outF[(size_t)gm * HIDDEN + gn]       = v0;
                *(float2*)&outF[(size_t)(gm + 8) * HIDDEN + gn] = v1;
            } else if (MODE == 1) {
                v0.x *= scale; v0.y *= scale; v1.x *= scale; v1.y *= scale;
                int h = gn >> 6, d = gn & 63;
                int b  = gm >> 11,       s  = gm & 2047;
                int b2 = (gm + 8) >> 11, s2 = (gm + 8) & 2047;
                size_t i0 = (((size_t)b  * NHEADS + h) * SEQ + s ) * HDIM + d;
                size_t i1 = (((size_t)b2 * NHEADS + h) * SEQ + s2) * HDIM + d;
                uint32_t hi, lo;
                split2(v0.x, v0.y, hi, lo);
                *(uint32_t*)&outH[i0] = hi; *(uint32_t*)&outL[i0] = lo;
                split2(v1.x, v1.y, hi, lo);
                *(uint32_t*)&outH[i1] = hi; *(uint32_t*)&outL[i1] = lo;
            } else {
                // transposed V planes [BH][D][S], scalar bf16 stores
                int h = gn >> 6, d = gn & 63;
                int b  = gm >> 11,       s  = gm & 2047;
                int b2 = (gm + 8) >> 11, s2 = (gm + 8) & 2047;
                size_t bh0 = (size_t)b  * NHEADS + h;
                size_t bh1 = (size_t)b2 * NHEADS + h;
                float vv[4] = {v0.x, v0.y, v1.x, v1.y};
                int   ss[4] = {s, s, s2, s2};
                size_t bb[4] = {bh0, bh0, bh1, bh1};
                int   dd[4] = {d, d + 1, d, d + 1};
                #pragma unroll
                for (int e = 0; e < 4; e++) {
                    __nv_bfloat16 hb = __float2bfloat16_rn(vv[e]);
                    __nv_bfloat16 lb = __float2bfloat16_rn(vv[e] - __bfloat162float(hb));
                    size_t idx = (bb[e] * HDIM + dd[e]) * SEQ + ss[e];
                    outH[idx] = hb;
                    outL[idx] = lb;
                }
            }
        }
    }
}

// ---------------------------------------------------------------------------
// Tensor-core flash attention, zero in-loop conversion.
// KV tiles arrive as prepacked bf16 hi/lo planes via cp.async (double buffer).
// Per buffer: Khi|Klo [64][72] + Vthi|Vtlo [64][72] = 36864 B; x2 = 73728 B.
// Q fragments loaded directly from gmem planes (pre-scaled 1/8).
// ---------------------------------------------------------------------------
__global__ __launch_bounds__(256)
void flash_attn_mma()
{
    constexpr int ST = 72;                   // smem row stride in halves (144 B)
    constexpr int BUFB = 36864;              // bytes per buffer
    extern __shared__ char smc[];

    const int tid  = threadIdx.x;
    const int lane = tid & 31, warp = tid >> 5;
    const int fr = lane >> 2, fc = lane & 3;
    const int q0 = blockIdx.x * 128;
    const int bh = blockIdx.y;

    const uint32_t smem0 = s2u(smc);

    const __nv_bfloat16* Kh = g_Kbh + (size_t)bh * SEQ * HDIM;
    const __nv_bfloat16* Kl = g_Kbl + (size_t)bh * SEQ * HDIM;
    const __nv_bfloat16* Vh = g_Vbh + (size_t)bh * HDIM * SEQ;
    const __nv_bfloat16* Vl = g_Vbl + (size_t)bh * HDIM * SEQ;

    // per-thread cp.async chunk slots: 2048 chunks = 4 planes x 64 rows x 8 segs
    // id = i*256+tid; plane = id>>9; w = id&511; row = w>>3; seg = w&7
    // issue one tile into buffer `bsel`
    auto issue_tile = [&](int t, int bsel) {
        const uint32_t base = smem0 + bsel * BUFB;
        #pragma unroll
        for (int i = 0; i < 8; i++) {
            int id = i * 256 + tid;
            int plane = id >> 9, w = id & 511;
            int row = w >> 3, seg = w & 7;
            uint32_t dst = base + plane * 9216 + row * 144 + seg * 16;
            const __nv_bfloat16* src;
            if (plane == 0)      src = Kh + (size_t)(t * 64 + row) * HDIM + seg * 8;
            else if (plane == 1) src = Kl + (size_t)(t * 64 + row) * HDIM + seg * 8;
            else if (plane == 2) src = Vh + (size_t)row * SEQ + t * 64 + seg * 8;
            else                 src = Vl + (size_t)row * SEQ + t * 64 + seg * 8;
            cp_async16(dst, src);
        }
        cp_commit();
    };

    // ---- Q fragments straight from gmem (prescaled by GEMM epilogue) ----
    uint32_t qhi[4][4], qlo[4][4];
    {
        const __nv_bfloat16* Qh = g_Qbh + (size_t)bh * SEQ * HDIM;
        const __nv_bfloat16* Ql = g_Qbl + (size_t)bh * SEQ * HDIM;
        const int q = q0 + warp * 16 + fr;
        #pragma unroll
        for (int kk = 0; kk < 4; kk++) {
            const __nv_bfloat16* p0 = &Qh[(size_t)q * HDIM + kk * 16 + fc * 2];
            const __nv_bfloat16* p1 = &Ql[(size_t)q * HDIM + kk * 16 + fc * 2];
            qhi[kk][0] = *(const uint32_t*)p0;
            qhi[kk][1] = *(const uint32_t*)(p0 + 8 * HDIM);
            qhi[kk][2] = *(const uint32_t*)(p0 + 8);
            qhi[kk][3] = *(const uint32_t*)(p0 + 8 * HDIM + 8);
            qlo[kk][0] = *(const uint32_t*)p1;
            qlo[kk][1] = *(const uint32_t*)(p1 + 8 * HDIM);
            qlo[kk][2] = *(const uint32_t*)(p1 + 8);
            qlo[kk][3] = *(const uint32_t*)(p1 + 8 * HDIM + 8);
        }
    }

    // prologue: tile 0 into buf 0
    issue_tile(0, 0);
    cp_wait0();
    __syncthreads();

    float o[8][4] = {};
    float m0r = -1e30f, m1r = -1e30f, l0r = 0.f, l1r = 0.f;

    for (int t = 0; t < SEQ / 64; t++) {
        const bool more = (t + 1 < SEQ / 64);
        if (more) issue_tile(t + 1, (t + 1) & 1);

        __nv_bfloat16* buf  = (__nv_bfloat16*)(smc + (t & 1) * BUFB);
        __nv_bfloat16* Khi  = buf;
        __nv_bfloat16* Klo  = buf + 4608;
        __nv_bfloat16* Vthi = buf + 9216;
        __nv_bfloat16* Vtlo = buf + 13824;

        // ---- S = Q K^T (3 passes) ----
        float s[8][4] = {};
        #pragma unroll
        for (int kk = 0; kk < 4; kk++) {
            #pragma unroll
            for (int ni = 0; ni < 8; ni++) {
                uint32_t bh2[2], bl2[2];
                const __nv_bfloat16* pb = &Khi[(ni * 8 + fr) * ST + kk * 16 + fc * 2];
                const __nv_bfloat16* pl = &Klo[(ni * 8 + fr) * ST + kk * 16 + fc * 2];
                bh2[0] = *(const uint32_t*)pb; bh2[1] = *(const uint32_t*)(pb + 8);
                bl2[0] = *(const uint32_t*)pl; bl2[1] = *(const uint32_t*)(pl + 8);
                mma16816(s[ni], qhi[kk], bh2);
                mma16816(s[ni], qhi[kk], bl2);
                mma16816(s[ni], qlo[kk], bh2);
            }
        }

        // ---- online softmax (registers + quad shfl only) ----
        float tmax0 = -1e30f, tmax1 = -1e30f;
        #pragma unroll
        for (int ni = 0; ni < 8; ni++) {
            tmax0 = fmaxf(tmax0, fmaxf(s[ni][0], s[ni][1]));
            tmax1 = fmaxf(tmax1, fmaxf(s[ni][2], s[ni][3]));
        }
        tmax0 = fmaxf(tmax0, __shfl_xor_sync(0xffffffffu, tmax0, 1));
        tmax0 = fmaxf(tmax0, __shfl_xor_sync(0xffffffffu, tmax0, 2));
        tmax1 = fmaxf(tmax1, __shfl_xor_sync(0xffffffffu, tmax1, 1));
        tmax1 = fmaxf(tmax1, __shfl_xor_sync(0xffffffffu, tmax1, 2));

        float mn0 = fmaxf(m0r, tmax0), mn1 = fmaxf(m1r, tmax1);
        float a0 = __expf(m0r - mn0),  a1 = __expf(m1r - mn1);
        m0r = mn0; m1r = mn1;

        float sum0 = 0.f, sum1 = 0.f;
        uint32_t phi[8][2], plo[8][2];
        #pragma unroll
        for (int ni = 0; ni < 8; ni++) {
            float p00 = __expf(s[ni][0] - mn0), p01 = __expf(s[ni][1] - mn0);
            float p10 = __expf(s[ni][2] - mn1), p11 = __expf(s[ni][3] - mn1);
            sum0 += p00 + p01; sum1 += p10 + p11;
            split2(p00, p01, phi[ni][0], plo[ni][0]);
            split2(p10, p11, phi[ni][1], plo[ni][1]);
        }
        sum0 += __shfl_xor_sync(0xffffffffu, sum0, 1);
        sum0 += __shfl_xor_sync(0xffffffffu, sum0, 2);
        sum1 += __shfl_xor_sync(0xffffffffu, sum1, 1);
        sum1 += __shfl_xor_sync(0xffffffffu, sum1, 2);
        l0r = l0r * a0 + sum0;
        l1r = l1r * a1 + sum1;

        #pragma unroll
        for (int ni = 0; ni < 8; ni++) {
            o[ni][0] *= a0; o[ni][1] *= a0;
            o[ni][2] *= a1; o[ni][3] *= a1;
        }

        // ---- O += P V (3 passes) ----
        #pragma unroll
        for (int kk = 0; kk < 4; kk++) {
            uint32_t ahz[4] = {phi[2*kk][0], phi[2*kk][1],
                               phi[2*kk+1][0], phi[2*kk+1][1]};
            uint32_t alz[4] = {plo[2*kk][0], plo[2*kk][1],
                               plo[2*kk+1][0], plo[2*kk+1][1]};
            #pragma unroll
            for (int nd = 0; nd < 8; nd++) {
                uint32_t bh2[2], bl2[2];
                const __nv_bfloat16* pb = &Vthi[(nd * 8 + fr) * ST + kk * 16 + fc * 2];
                const __nv_bfloat16* pl = &Vtlo[(nd * 8 + fr) * ST + kk * 16 + fc * 2];
                bh2[0] = *(const uint32_t*)pb; bh2[1] = *(const uint32_t*)(pb + 8);
                bl2[0] = *(const uint32_t*)pl; bl2[1] = *(const uint32_t*)(pl + 8);
                mma16816(o[nd], ahz, bh2);
                mma16816(o[nd], ahz, bl2);
                mma16816(o[nd], alz, bh2);
            }
        }

        if (more) cp_wait0();
        __syncthreads();
    }

    // ---- normalize, write ctx [B,S,HIDDEN] ----
    const int b = bh / NHEADS, h = bh % NHEADS;
    const float inv0 = 1.0f / l0r, inv1 = 1.0f / l1r;
    const int q = q0 + warp * 16 + fr;
    #pragma unroll
    for (int nd = 0; nd < 8; nd++) {
        int d = h * HDIM + nd * 8 + fc * 2;
        float2 v0 = make_float2(o[nd][0] * inv0, o[nd][1] * inv0);
        float2 v1 = make_float2(o[nd][2] * inv1, o[nd][3] * inv1);
        *(float2*)&g_ctx[((size_t)b * SEQ + q    ) * HIDDEN + d] = v0;
        *(float2*)&g_ctx[((size_t)b * SEQ + q + 8) * HIDDEN + d] = v1;
    }
}

// ---------------------------------------------------------------------------
extern "C" void kernel_launch(void* const* d_in, const int* in_sizes, int n_in,
                              void* d_out, int out_size)
{
    const float* query = (const float*)d_in[0];
    const float* key   = (const float*)d_in[1];
    const float* value = (const float*)d_in[2];
    const float* Wq = (const float*)d_in[3];
    const float* bq = (const float*)d_in[4];
    const float* Wk = (const float*)d_in[5];
    const float* bk = (const float*)d_in[6];
    const float* Wv = (const float*)d_in[7];
    const float* bv = (const float*)d_in[8];
    const float* Wo = (const float*)d_in[9];
    const float* bo = (const float*)d_in[10];

    float* gctx;
    __nv_bfloat16 *qh, *ql, *kh, *kl, *vh, *vl;
    cudaGetSymbolAddress((void**)&gctx, g_ctx);
    cudaGetSymbolAddress((void**)&qh, g_Qbh);
    cudaGetSymbolAddress((void**)&ql, g_Qbl);
    cudaGetSymbolAddress((void**)&kh, g_Kbh);
    cudaGetSymbolAddress((void**)&kl, g_Kbl);
    cudaGetSymbolAddress((void**)&vh, g_Vbh);
    cudaGetSymbolAddress((void**)&vl, g_Vbl);

    dim3 ggrid(HIDDEN / 128, MROWS / 128);   // (8, 32)
    const int gsmem = 4 * 128 * 40 * 2;      // 40960 B

    gemm_bf16x2<1><<<ggrid, 256, gsmem>>>(query, Wq, bq, nullptr, qh, ql, 0.125f);
    gemm_bf16x2<1><<<ggrid, 256, gsmem>>>(key,   Wk, bk, nullptr, kh, kl, 1.0f);
    gemm_bf16x2<2><<<ggrid, 256, gsmem>>>(value, Wv, bv, nullptr, vh, vl, 1.0f);

    const int fsmem = 2 * 36864;             // 73728 B
    cudaFuncSetAttribute(flash_attn_mma,
                         cudaFuncAttributeMaxDynamicSharedMemorySize, fsmem);
    flash_attn_mma<<<dim3(SEQ / 128, BATCH * NHEADS), 256, fsmem>>>();

    gemm_bf16x2<0><<<ggrid, 256, gsmem>>>(gctx, Wo, bo, (float*)d_out,
                                          nullptr, nullptr, 1.0f);
}

// round 15
// speedup vs baseline: 1.0769x; 1.0769x over previous
#include <cuda_runtime.h>
#include <cuda_bf16.h>
#include <cstdint>

#define HIDDEN 1024
#define NHEADS 16
#define HDIM   64
#define BATCH  2
#define SEQ    2048
#define MROWS  (BATCH*SEQ)   // 4096

// fp32 ctx scratch
__device__ float g_ctx[MROWS*HIDDEN];
// bf16 hi/lo planes produced by projection GEMM epilogues
__device__ __nv_bfloat16 g_Qbh[MROWS*HIDDEN];   // [BH][S][D], pre-scaled 1/8
__device__ __nv_bfloat16 g_Qbl[MROWS*HIDDEN];
__device__ __nv_bfloat16 g_Kbh[MROWS*HIDDEN];   // [BH][S][D]
__device__ __nv_bfloat16 g_Kbl[MROWS*HIDDEN];
__device__ __nv_bfloat16 g_Vsh[MROWS*HIDDEN];   // [BH][S][D]  (natural)
__device__ __nv_bfloat16 g_Vsl[MROWS*HIDDEN];
__device__ __nv_bfloat16 g_Vbh[MROWS*HIDDEN];   // [BH][D][S]  (transposed)
__device__ __nv_bfloat16 g_Vbl[MROWS*HIDDEN];

// ---------------------------------------------------------------------------
__device__ __forceinline__ void mma16816(float* c, const uint32_t* a,
                                         const uint32_t* b)
{
    asm volatile(
        "mma.sync.aligned.m16n8k16.row.col.f32.bf16.bf16.f32 "
        "{%0,%1,%2,%3}, {%4,%5,%6,%7}, {%8,%9}, {%0,%1,%2,%3};"
        : "+f"(c[0]), "+f"(c[1]), "+f"(c[2]), "+f"(c[3])
        : "r"(a[0]), "r"(a[1]), "r"(a[2]), "r"(a[3]), "r"(b[0]), "r"(b[1]));
}

__device__ __forceinline__ uint32_t pack_bf16(__nv_bfloat16 lo, __nv_bfloat16 hi)
{
    __nv_bfloat162 t = __halves2bfloat162(lo, hi);
    return *(uint32_t*)&t;
}

__device__ __forceinline__ void split2(float x, float y,
                                       uint32_t& hi, uint32_t& lo)
{
    __nv_bfloat16 hx = __float2bfloat16_rn(x), hy = __float2bfloat16_rn(y);
    __nv_bfloat16 lx = __float2bfloat16_rn(x - __bfloat162float(hx));
    __nv_bfloat16 ly = __float2bfloat16_rn(y - __bfloat162float(hy));
    hi = pack_bf16(hx, hy);
    lo = pack_bf16(lx, ly);
}

__device__ __forceinline__ uint32_t s2u(const void* p) {
    uint32_t a;
    asm("{ .reg .u64 t; cvta.to.shared.u64 t, %1; cvt.u32.u64 %0, t; }"
        : "=r"(a) : "l"(p));
    return a;
}
__device__ __forceinline__ void cp_async16(uint32_t dst, const void* src) {
    asm volatile("cp.async.cg.shared.global [%0], [%1], 16;"
                 :: "r"(dst), "l"(src) : "memory");
}
__device__ __forceinline__ void cp_commit() {
    asm volatile("cp.async.commit_group;" ::: "memory");
}
__device__ __forceinline__ void cp_wait0() {
    asm volatile("cp.async.wait_group 0;" ::: "memory");
}

// ---------------------------------------------------------------------------
// C[4096,1024] = X @ W^T + bias via bf16 hi/lo split (3 MMA passes).
//  MODE 0: fp32 row-major to outF
//  MODE 1: bf16 hi/lo planes [BH][S][D], value = (acc+bias)*scale  (coalesced)
// ---------------------------------------------------------------------------
template<int MODE>
__global__ __launch_bounds__(256)
void gemm_bf16x2(const float* __restrict__ X, const float* __restrict__ W,
                 const float* __restrict__ bias, float* __restrict__ outF,
                 __nv_bfloat16* __restrict__ outH,
                 __nv_bfloat16* __restrict__ outL, float scale)
{
    constexpr int BK = 32, ST = 40;
    extern __shared__ __nv_bfloat16 smb[];
    __nv_bfloat16* Ah = smb;
    __nv_bfloat16* Al = Ah + 128 * ST;
    __nv_bfloat16* Bh = Al + 128 * ST;
    __nv_bfloat16* Bl = Bh + 128 * ST;

    const int tid  = threadIdx.x;
    const int lane = tid & 31, warp = tid >> 5;
    const int wr = warp >> 2, wc = warp & 3;
    const int row0 = blockIdx.y * 128, col0 = blockIdx.x * 128;
    const int m0 = wr * 64, n0 = wc * 32;
    const int fr = lane >> 2, fc = lane & 3;

    float acc[4][4][4] = {};
    const int gr = tid >> 3, gc4 = tid & 7;

    for (int k0 = 0; k0 < HIDDEN; k0 += BK) {
        #pragma unroll
        for (int i = 0; i < 4; i++) {
            int r = gr + i * 32;
            float4 v = *(const float4*)&X[(size_t)(row0 + r) * HIDDEN + k0 + gc4 * 4];
            uint32_t h0, l0, h1, l1;
            split2(v.x, v.y, h0, l0); split2(v.z, v.w, h1, l1);
            *(uint32_t*)&Ah[r * ST + gc4 * 4]     = h0;
            *(uint32_t*)&Ah[r * ST + gc4 * 4 + 2] = h1;
            *(uint32_t*)&Al[r * ST + gc4 * 4]     = l0;
            *(uint32_t*)&Al[r * ST + gc4 * 4 + 2] = l1;

            v = *(const float4*)&W[(size_t)(col0 + r) * HIDDEN + k0 + gc4 * 4];
            split2(v.x, v.y, h0, l0); split2(v.z, v.w, h1, l1);
            *(uint32_t*)&Bh[r * ST + gc4 * 4]     = h0;
            *(uint32_t*)&Bh[r * ST + gc4 * 4 + 2] = h1;
            *(uint32_t*)&Bl[r * ST + gc4 * 4]     = l0;
            *(uint32_t*)&Bl[r * ST + gc4 * 4 + 2] = l1;
        }
        __syncthreads();

        #pragma unroll
        for (int ks = 0; ks < BK; ks += 16) {
            uint32_t ah[4][4], al[4][4], bh[4][2], bl[4][2];
            #pragma unroll
            for (int mi = 0; mi < 4; mi++) {
                const __nv_bfloat16* pa = &Ah[(m0 + mi * 16 + fr) * ST + ks + fc * 2];
                const __nv_bfloat16* pl = &Al[(m0 + mi * 16 + fr) * ST + ks + fc * 2];
                ah[mi][0] = *(const uint32_t*)pa;
                ah[mi][1] = *(const uint32_t*)(pa + 8 * ST);
                ah[mi][2] = *(const uint32_t*)(pa + 8);
                ah[mi][3] = *(const uint32_t*)(pa + 8 * ST + 8);
                al[mi][0] = *(const uint32_t*)pl;
                al[mi][1] = *(const uint32_t*)(pl + 8 * ST);
                al[mi][2] = *(const uint32_t*)(pl + 8);
                al[mi][3] = *(const uint32_t*)(pl + 8 * ST + 8);
            }
            #pragma unroll
            for (int ni = 0; ni < 4; ni++) {
                const __nv_bfloat16* pb = &Bh[(n0 + ni * 8 + fr) * ST + ks + fc * 2];
                const __nv_bfloat16* pl = &Bl[(n0 + ni * 8 + fr) * ST + ks + fc * 2];
                bh[ni][0] = *(const uint32_t*)pb;
                bh[ni][1] = *(const uint32_t*)(pb + 8);
                bl[ni][0] = *(const uint32_t*)pl;
                bl[ni][1] = *(const uint32_t*)(pl + 8);
            }
            #pragma unroll
            for (int mi = 0; mi < 4; mi++)
                #pragma unroll
                for (int ni = 0; ni < 4; ni++) {
                    mma16816(acc[mi][ni], ah[mi], bh[ni]);
                    mma16816(acc[mi][ni], ah[mi], bl[ni]);
                    mma16816(acc[mi][ni], al[mi], bh[ni]);
                }
        }
        __syncthreads();
    }

    #pragma unroll
    for (int mi = 0; mi < 4; mi++) {
        #pragma unroll
        for (int ni = 0; ni < 4; ni++) {
            int gm = row0 + m0 + mi * 16 + fr;
            int gn = col0 + n0 + ni * 8 + fc * 2;
            float b0 = bias[gn], b1 = bias[gn + 1];
            float2 v0 = make_float2(acc[mi][ni][0] + b0, acc[mi][ni][1] + b1);
            float2 v1 = make_float2(acc[mi][ni][2] + b0, acc[mi][ni][3] + b1);
            if (MODE == 0) {
                *(float2*)&outF[(size_t)gm * HIDDEN + gn]       = v0;
                *(float2*)&outF[(size_t)(gm + 8) * HIDDEN + gn] = v1;
            } else {
                v0.x *= scale; v0.y *= scale; v1.x *= scale; v1.y *= scale;
                int h = gn >> 6, d = gn & 63;
                int b  = gm >> 11,       s  = gm & 2047;
                int b2 = (gm + 8) >> 11, s2 = (gm + 8) & 2047;
                size_t i0 = (((size_t)b  * NHEADS + h) * SEQ + s ) * HDIM + d;
                size_t i1 = (((size_t)b2 * NHEADS + h) * SEQ + s2) * HDIM + d;
                uint32_t hi, lo;
                split2(v0.x, v0.y, hi, lo);
                *(uint32_t*)&outH[i0] = hi; *(uint32_t*)&outL[i0] = lo;
                split2(v1.x, v1.y, hi, lo);
                *(uint32_t*)&outH[i1] = hi; *(uint32_t*)&outL[i1] = lo;
            }
        }
    }
}

// ---------------------------------------------------------------------------
// Transpose bf16 plane [BH][S][D] -> [BH][D][S], smem-tiled, coalesced both
// sides. grid = (SEQ/64, BH, 2); z selects hi/lo plane.
// ---------------------------------------------------------------------------
__global__ __launch_bounds__(256)
void vt_transpose()
{
    __shared__ __nv_bfloat16 tile[64 * 68];
    const int tid = threadIdx.x;
    const int t   = blockIdx.x;
    const int bh  = blockIdx.y;
    const __nv_bfloat16* in  = blockIdx.z ? g_Vsl : g_Vsh;
    __nv_bfloat16*       out = blockIdx.z ? g_Vbl : g_Vbh;
    const __nv_bfloat16* src = in  + ((size_t)bh * SEQ + t * 64) * HDIM;
    __nv_bfloat16*       dst = out + (size_t)bh * HDIM * SEQ + t * 64;

    #pragma unroll
    for (int i = 0; i < 8; i++) {
        int idx = i * 256 + tid;          // 2048 u32 loads
        int s = idx >> 5, d2 = idx & 31;
        *(uint32_t*)&tile[s * 68 + d2 * 2] =
            *(const uint32_t*)&src[(size_t)s * HDIM + d2 * 2];
    }
    __syncthreads();
    #pragma unroll
    for (int i = 0; i < 8; i++) {
        int idx = i * 256 + tid;          // 2048 u32 stores
        int d = idx >> 5, sp = idx & 31;
        __nv_bfloat16 a = tile[(2 * sp)     * 68 + d];
        __nv_bfloat16 b = tile[(2 * sp + 1) * 68 + d];
        *(uint32_t*)&dst[(size_t)d * SEQ + 2 * sp] = pack_bf16(a, b);
    }
}

// ---------------------------------------------------------------------------
// Tensor-core flash attention, zero in-loop conversion, 2 CTAs/SM.
// KV tiles arrive as prepacked bf16 hi/lo planes via cp.async (double buffer).
// Per buffer: Khi|Klo [64][72] + Vthi|Vtlo [64][72] = 36864 B; x2 = 73728 B.
// __launch_bounds__(256, 2): cap 128 regs -> 2 CTA/SM (smem 147456 <= 228K).
// ---------------------------------------------------------------------------
__global__ __launch_bounds__(256, 2)
void flash_attn_mma()
{
    constexpr int ST = 72;                   // smem row stride in halves (144 B)
    constexpr int BUFB = 36864;              // bytes per buffer
    extern __shared__ char smc[];

    const int tid  = threadIdx.x;
    const int lane = tid & 31, warp = tid >> 5;
    const int fr = lane >> 2, fc = lane & 3;
    const int q0 = blockIdx.x * 128;
    const int bh = blockIdx.y;

    const uint32_t smem0 = s2u(smc);

    const __nv_bfloat16* Kh = g_Kbh + (size_t)bh * SEQ * HDIM;
    const __nv_bfloat16* Kl = g_Kbl + (size_t)bh * SEQ * HDIM;
    const __nv_bfloat16* Vh = g_Vbh + (size_t)bh * HDIM * SEQ;
    const __nv_bfloat16* Vl = g_Vbl + (size_t)bh * HDIM * SEQ;

    auto issue_tile = [&](int t, int bsel) {
        const uint32_t base = smem0 + bsel * BUFB;
        #pragma unroll
        for (int i = 0; i < 8; i++) {
            int id = i * 256 + tid;
            int plane = id >> 9, w = id & 511;
            int row = w >> 3, seg = w & 7;
            uint32_t dst = base + plane * 9216 + row * 144 + seg * 16;
            const __nv_bfloat16* src;
            if (plane == 0)      src = Kh + (size_t)(t * 64 + row) * HDIM + seg * 8;
            else if (plane == 1) src = Kl + (size_t)(t * 64 + row) * HDIM + seg * 8;
            else if (plane == 2) src = Vh + (size_t)row * SEQ + t * 64 + seg * 8;
            else                 src = Vl + (size_t)row * SEQ + t * 64 + seg * 8;
            cp_async16(dst, src);
        }
        cp_commit();
    };

    // ---- Q fragments straight from gmem (prescaled by GEMM epilogue) ----
    uint32_t qhi[4][4], qlo[4][4];
    {
        const __nv_bfloat16* Qh = g_Qbh + (size_t)bh * SEQ * HDIM;
        const __nv_bfloat16* Ql = g_Qbl + (size_t)bh * SEQ * HDIM;
        const int q = q0 + warp * 16 + fr;
        #pragma unroll
        for (int kk = 0; kk < 4; kk++) {
            const __nv_bfloat16* p0 = &Qh[(size_t)q * HDIM + kk * 16 + fc * 2];
            const __nv_bfloat16* p1 = &Ql[(size_t)q * HDIM + kk * 16 + fc * 2];
            qhi[kk][0] = *(const uint32_t*)p0;
            qhi[kk][1] = *(const uint32_t*)(p0 + 8 * HDIM);
            qhi[kk][2] = *(const uint32_t*)(p0 + 8);
            qhi[kk][3] = *(const uint32_t*)(p0 + 8 * HDIM + 8);
            qlo[kk][0] = *(const uint32_t*)p1;
            qlo[kk][1] = *(const uint32_t*)(p1 + 8 * HDIM);
            qlo[kk][2] = *(const uint32_t*)(p1 + 8);
            qlo[kk][3] = *(const uint32_t*)(p1 + 8 * HDIM + 8);
        }
    }

    issue_tile(0, 0);
    cp_wait0();
    __syncthreads();

    float o[8][4] = {};
    float m0r = -1e30f, m1r = -1e30f, l0r = 0.f, l1r = 0.f;

    for (int t = 0; t < SEQ / 64; t++) {
        const bool more = (t + 1 < SEQ / 64);
        if (more) issue_tile(t + 1, (t + 1) & 1);

        __nv_bfloat16* buf  = (__nv_bfloat16*)(smc + (t & 1) * BUFB);
        __nv_bfloat16* Khi  = buf;
        __nv_bfloat16* Klo  = buf + 4608;
        __nv_bfloat16* Vthi = buf + 9216;
        __nv_bfloat16* Vtlo = buf + 13824;

        // ---- S = Q K^T (3 passes) ----
        float s[8][4] = {};
        #pragma unroll
        for (int kk = 0; kk < 4; kk++) {
            #pragma unroll
            for (int ni = 0; ni < 8; ni++) {
                uint32_t bh2[2], bl2[2];
                const __nv_bfloat16* pb = &Khi[(ni * 8 + fr) * ST + kk * 16 + fc * 2];
                const __nv_bfloat16* pl = &Klo[(ni * 8 + fr) * ST + kk * 16 + fc * 2];
                bh2[0] = *(const uint32_t*)pb; bh2[1] = *(const uint32_t*)(pb + 8);
                bl2[0] = *(const uint32_t*)pl; bl2[1] = *(const uint32_t*)(pl + 8);
                mma16816(s[ni], qhi[kk], bh2);
                mma16816(s[ni], qhi[kk], bl2);
                mma16816(s[ni], qlo[kk], bh2);
            }
        }

        // ---- online softmax (registers + quad shfl only) ----
        float tmax0 = -1e30f, tmax1 = -1e30f;
        #pragma unroll
        for (int ni = 0; ni < 8; ni++) {
            tmax0 = fmaxf(tmax0, fmaxf(s[ni][0], s[ni][1]));
            tmax1 = fmaxf(tmax1, fmaxf(s[ni][2], s[ni][3]));
        }
        tmax0 = fmaxf(tmax0, __shfl_xor_sync(0xffffffffu, tmax0, 1));
        tmax0 = fmaxf(tmax0, __shfl_xor_sync(0xffffffffu, tmax0, 2));
        tmax1 = fmaxf(tmax1, __shfl_xor_sync(0xffffffffu, tmax1, 1));
        tmax1 = fmaxf(tmax1, __shfl_xor_sync(0xffffffffu, tmax1, 2));

        float mn0 = fmaxf(m0r, tmax0), mn1 = fmaxf(m1r, tmax1);
        float a0 = __expf(m0r - mn0),  a1 = __expf(m1r - mn1);
        m0r = mn0; m1r = mn1;

        float sum0 = 0.f, sum1 = 0.f;
        uint32_t phi[8][2], plo[8][2];
        #pragma unroll
        for (int ni = 0; ni < 8; ni++) {
            float p00 = __expf(s[ni][0] - mn0), p01 = __expf(s[ni][1] - mn0);
            float p10 = __expf(s[ni][2] - mn1), p11 = __expf(s[ni][3] - mn1);
            sum0 += p00 + p01; sum1 += p10 + p11;
            split2(p00, p01, phi[ni][0], plo[ni][0]);
            split2(p10, p11, phi[ni][1], plo[ni][1]);
        }
        sum0 += __shfl_xor_sync(0xffffffffu, sum0, 1);
        sum0 += __shfl_xor_sync(0xffffffffu, sum0, 2);
        sum1 += __shfl_xor_sync(0xffffffffu, sum1, 1);
        sum1 += __shfl_xor_sync(0xffffffffu, sum1, 2);
        l0r = l0r * a0 + sum0;
        l1r = l1r * a1 + sum1;

        #pragma unroll
        for (int ni = 0; ni < 8; ni++) {
            o[ni][0] *= a0; o[ni][1] *= a0;
            o[ni][2] *= a1; o[ni][3] *= a1;
        }

        // ---- O += P V (3 passes) ----
        #pragma unroll
        for (int kk = 0; kk < 4; kk++) {
            uint32_t ahz[4] = {phi[2*kk][0], phi[2*kk][1],
                               phi[2*kk+1][0], phi[2*kk+1][1]};
            uint32_t alz[4] = {plo[2*kk][0], plo[2*kk][1],
                               plo[2*kk+1][0], plo[2*kk+1][1]};
            #pragma unroll
            for (int nd = 0; nd < 8; nd++) {
                uint32_t bh2[2], bl2[2];
                const __nv_bfloat16* pb = &Vthi[(nd * 8 + fr) * ST + kk * 16 + fc * 2];
                const __nv_bfloat16* pl = &Vtlo[(nd * 8 + fr) * ST + kk * 16 + fc * 2];
                bh2[0] = *(const uint32_t*)pb; bh2[1] = *(const uint32_t*)(pb + 8);
                bl2[0] = *(const uint32_t*)pl; bl2[1] = *(const uint32_t*)(pl + 8);
                mma16816(o[nd], ahz, bh2);
                mma16816(o[nd], ahz, bl2);
                mma16816(o[nd], alz, bh2);
            }
        }

        if (more) cp_wait0();
        __syncthreads();
    }

    // ---- normalize, write ctx [B,S,HIDDEN] ----
    const int b = bh / NHEADS, h = bh % NHEADS;
    const float inv0 = 1.0f / l0r, inv1 = 1.0f / l1r;
    const int q = q0 + warp * 16 + fr;
    #pragma unroll
    for (int nd = 0; nd < 8; nd++) {
        int d = h * HDIM + nd * 8 + fc * 2;
        float2 v0 = make_float2(o[nd][0] * inv0, o[nd][1] * inv0);
        float2 v1 = make_float2(o[nd][2] * inv1, o[nd][3] * inv1);
        *(float2*)&g_ctx[((size_t)b * SEQ + q    ) * HIDDEN + d] = v0;
        *(float2*)&g_ctx[((size_t)b * SEQ + q + 8) * HIDDEN + d] = v1;
    }
}

// ---------------------------------------------------------------------------
extern "C" void kernel_launch(void* const* d_in, const int* in_sizes, int n_in,
                              void* d_out, int out_size)
{
    const float* query = (const float*)d_in[0];
    const float* key   = (const float*)d_in[1];
    const float* value = (const float*)d_in[2];
    const float* Wq = (const float*)d_in[3];
    const float* bq = (const float*)d_in[4];
    const float* Wk = (const float*)d_in[5];
    const float* bk = (const float*)d_in[6];
    const float* Wv = (const float*)d_in[7];
    const float* bv = (const float*)d_in[8];
    const float* Wo = (const float*)d_in[9];
    const float* bo = (const float*)d_in[10];

    float* gctx;
    __nv_bfloat16 *qh, *ql, *kh, *kl, *vsh, *vsl;
    cudaGetSymbolAddress((void**)&gctx, g_ctx);
    cudaGetSymbolAddress((void**)&qh,  g_Qbh);
    cudaGetSymbolAddress((void**)&ql,  g_Qbl);
    cudaGetSymbolAddress((void**)&kh,  g_Kbh);
    cudaGetSymbolAddress((void**)&kl,  g_Kbl);
    cudaGetSymbolAddress((void**)&vsh, g_Vsh);
    cudaGetSymbolAddress((void**)&vsl, g_Vsl);

    dim3 ggrid(HIDDEN / 128, MROWS / 128);   // (8, 32)
    const int gsmem = 4 * 128 * 40 * 2;      // 40960 B

    gemm_bf16x2<1><<<ggrid, 256, gsmem>>>(query, Wq, bq, nullptr, qh, ql, 0.125f);
    gemm_bf16x2<1><<<ggrid, 256, gsmem>>>(key,   Wk, bk, nullptr, kh, kl, 1.0f);
    gemm_bf16x2<1><<<ggrid, 256, gsmem>>>(value, Wv, bv, nullptr, vsh, vsl, 1.0f);

    vt_transpose<<<dim3(SEQ / 64, BATCH * NHEADS, 2), 256>>>();

    const int fsmem = 2 * 36864;             // 73728 B
    cudaFuncSetAttribute(flash_attn_mma,
                         cudaFuncAttributeMaxDynamicSharedMemorySize, fsmem);
    flash_attn_mma<<<dim3(SEQ / 128, BATCH * NHEADS), 256, fsmem>>>();

    gemm_bf16x2<0><<<ggrid, 256, gsmem>>>(gctx, Wo, bo, (float*)d_out,
                                          nullptr, nullptr, 1.0f);
}